// round 3
// baseline (speedup 1.0000x reference)
#include <cuda_runtime.h>

#define NV   2000000
#define NC   2000
#define NE   16000
#define HID  128
#define LAT  64

// Scratch: cluster accumulators (no cudaMalloc allowed).
__device__ float4 g_sum4[NC];
__device__ float  g_cnt[NC];

// ---------------------------------------------------------------------------
// Kernel 1: segment sum via global vector reductions.
// Each thread handles 4 voxels per iteration: 5x LDG.128 for data,
// 1x LDG.128 for the 4 cluster ids, then per voxel:
//   red.global.add.v4.f32  (sums)  +  scalar REDG (count).
// Fire-and-forget: no return value, no latency to hide, pure issue throughput.
// ---------------------------------------------------------------------------
__device__ __forceinline__ void red_v4(float4* addr, float a, float b, float c, float d) {
    asm volatile("red.global.add.v4.f32 [%0], {%1, %2, %3, %4};"
                 :: "l"(addr), "f"(a), "f"(b), "f"(c), "f"(d) : "memory");
}

__global__ __launch_bounds__(256) void k_seg(const float* __restrict__ data,
                                             const int*   __restrict__ cid) {
    const int NG = NV / 4;                       // 500,000 groups of 4 voxels
    const int stride = gridDim.x * 256;
    for (int g = blockIdx.x * 256 + threadIdx.x; g < NG; g += stride) {
        const float4* p = (const float4*)(data) + (size_t)g * 5;
        float4 q0 = __ldg(p + 0);
        float4 q1 = __ldg(p + 1);
        float4 q2 = __ldg(p + 2);
        float4 q3 = __ldg(p + 3);
        float4 q4 = __ldg(p + 4);
        int4 c = __ldg((const int4*)cid + g);

        // voxel layout: [d f0 f1 f2 f3] x4  (feature = cols 1..4)
        red_v4(&g_sum4[c.x], q0.y, q0.z, q0.w, q1.x);
        red_v4(&g_sum4[c.y], q1.z, q1.w, q2.x, q2.y);
        red_v4(&g_sum4[c.z], q2.w, q3.x, q3.y, q3.z);
        red_v4(&g_sum4[c.w], q4.x, q4.y, q4.z, q4.w);

        atomicAdd(&g_cnt[c.x], 1.f);
        atomicAdd(&g_cnt[c.y], 1.f);
        atomicAdd(&g_cnt[c.z], 1.f);
        atomicAdd(&g_cnt[c.w], 1.f);
    }
}

// ---------------------------------------------------------------------------
// Kernel 2: edge gather + 2-layer MLP (unchanged structure from R1).
// One block = 64 edges, 128 threads.
//  Phase A: h[k][e] = relu(b1[k] + pooled[e] . W1[:,k])  (k-major in shared)
//  Phase B: register-tiled GEMM  out[e][n] = h[e][:] . W2[:,n] + b2[n]
// ---------------------------------------------------------------------------
__global__ __launch_bounds__(128) void k_mlp(const int*   __restrict__ eidx,
                                             const float* __restrict__ W1,
                                             const float* __restrict__ b1,
                                             const float* __restrict__ W2,
                                             const float* __restrict__ b2,
                                             float*       __restrict__ out) {
    extern __shared__ float sm[];
    float* s_W2   = sm;                 // 8192 floats  [128][64]
    float* s_h    = sm + 8192;          // 8192 floats  [128][64] (k-major)
    float* s_W1   = sm + 16384;         // 512 floats   [4][128]
    float* s_b1   = s_W1 + 512;         // 128
    float* s_b2   = s_b1 + 128;         // 64
    float* s_pool = s_b2 + 64;          // 256 floats   [64][4]

    const int t = threadIdx.x;

    for (int i = t; i < 8192 / 4; i += 128)
        ((float4*)s_W2)[i] = ((const float4*)W2)[i];
    for (int i = t; i < 512 / 4; i += 128)
        ((float4*)s_W1)[i] = ((const float4*)W1)[i];
    if (t < 128) s_b1[t] = b1[t];
    if (t < 64)  s_b2[t] = b2[t];

    const int base = blockIdx.x * 64;

    if (t < 64) {
        int e  = base + t;
        int a  = eidx[e];
        int b  = eidx[NE + e];
        float4 sa = g_sum4[a];
        float4 sb = g_sum4[b];
        float inv = 1.f / fmaxf(g_cnt[a] + g_cnt[b], 1.f);
        s_pool[t * 4 + 0] = (sa.x + sb.x) * inv;
        s_pool[t * 4 + 1] = (sa.y + sb.y) * inv;
        s_pool[t * 4 + 2] = (sa.z + sb.z) * inv;
        s_pool[t * 4 + 3] = (sa.w + sb.w) * inv;
    }
    __syncthreads();

    // Phase A
    {
        int e  = t & 63;
        int kh = (t >> 6) * 64;
        float p0 = s_pool[e * 4 + 0];
        float p1 = s_pool[e * 4 + 1];
        float p2 = s_pool[e * 4 + 2];
        float p3 = s_pool[e * 4 + 3];
#pragma unroll 4
        for (int j = 0; j < 64; j++) {
            int k = kh + j;
            float h = s_b1[k]
                    + p0 * s_W1[0 * 128 + k]
                    + p1 * s_W1[1 * 128 + k]
                    + p2 * s_W1[2 * 128 + k]
                    + p3 * s_W1[3 * 128 + k];
            s_h[k * 64 + e] = fmaxf(h, 0.f);
        }
    }
    __syncthreads();

    // Phase B
    const int tx = t & 15;
    const int ty = t >> 4;
    float acc[8][4];
#pragma unroll
    for (int i = 0; i < 8; i++)
#pragma unroll
        for (int j = 0; j < 4; j++) acc[i][j] = 0.f;

    const float4* hf4 = (const float4*)s_h;    // [128][16]
    const float4* wf4 = (const float4*)s_W2;   // [128][16]
#pragma unroll 2
    for (int k = 0; k < 128; k++) {
        float4 w  = wf4[k * 16 + tx];
        float4 ha = hf4[k * 16 + ty * 2];
        float4 hb = hf4[k * 16 + ty * 2 + 1];
        float hv[8] = {ha.x, ha.y, ha.z, ha.w, hb.x, hb.y, hb.z, hb.w};
#pragma unroll
        for (int i = 0; i < 8; i++) {
            acc[i][0] = fmaf(hv[i], w.x, acc[i][0]);
            acc[i][1] = fmaf(hv[i], w.y, acc[i][1]);
            acc[i][2] = fmaf(hv[i], w.z, acc[i][2]);
            acc[i][3] = fmaf(hv[i], w.w, acc[i][3]);
        }
    }

    float c0 = s_b2[tx * 4 + 0];
    float c1 = s_b2[tx * 4 + 1];
    float c2 = s_b2[tx * 4 + 2];
    float c3 = s_b2[tx * 4 + 3];
#pragma unroll
    for (int i = 0; i < 8; i++) {
        int e = base + ty * 8 + i;
        float4 o = make_float4(acc[i][0] + c0, acc[i][1] + c1,
                               acc[i][2] + c2, acc[i][3] + c3);
        ((float4*)out)[e * 16 + tx] = o;
    }
}

// ---------------------------------------------------------------------------
// Launch: memset accumulators -> segment sum -> edge MLP (graph-capturable)
// ---------------------------------------------------------------------------
extern "C" void kernel_launch(void* const* d_in, const int* in_sizes, int n_in,
                              void* d_out, int out_size) {
    const float* data = (const float*)d_in[0];
    const int*   cid  = (const int*)  d_in[1];
    const int*   eidx = (const int*)  d_in[2];
    const float* W1   = (const float*)d_in[3];
    const float* b1   = (const float*)d_in[4];
    const float* W2   = (const float*)d_in[5];
    const float* b2   = (const float*)d_in[6];
    float*       out  = (float*)d_out;

    cudaFuncSetAttribute(k_mlp, cudaFuncAttributeMaxDynamicSharedMemorySize, 70000);

    void *p_sum, *p_cnt;
    cudaGetSymbolAddress(&p_sum, g_sum4);
    cudaGetSymbolAddress(&p_cnt, g_cnt);
    cudaMemsetAsync(p_sum, 0, NC * sizeof(float4));
    cudaMemsetAsync(p_cnt, 0, NC * sizeof(float));

    k_seg<<<592, 256>>>(data, cid);
    k_mlp<<<NE / 64, 128, 69376>>>(eidx, W1, b1, W2, b2, out);
}

// round 4
// speedup vs baseline: 2.2689x; 2.2689x over previous
#include <cuda_runtime.h>

#define NV   2000000
#define NC   2000
#define NE   16000
#define HID  128
#define LAT  64

// Scratch: cluster accumulators (no cudaMalloc allowed).
__device__ float4 g_sum4[NC];
__device__ float  g_cnt[NC];

// ---------------------------------------------------------------------------
// Kernel 1: segment sum, shared-memory privatization (R1 winner) +
// vectorized loads (5x LDG.128 data + 1x LDG.128 ids per 4 voxels).
// Shared atomics spread over 2000 clusters; one global flush per block.
// ---------------------------------------------------------------------------
__global__ __launch_bounds__(256) void k_seg(const float* __restrict__ data,
                                             const int*   __restrict__ cid) {
    __shared__ float s_sum[NC * 4];   // 32 KB, layout == float4[NC]
    __shared__ float s_cnt[NC];       //  8 KB
    for (int i = threadIdx.x; i < NC * 4; i += 256) s_sum[i] = 0.f;
    for (int i = threadIdx.x; i < NC;     i += 256) s_cnt[i] = 0.f;
    __syncthreads();

    const int NG = NV / 4;
    const int stride = gridDim.x * 256;
    for (int g = blockIdx.x * 256 + threadIdx.x; g < NG; g += stride) {
        const float4* p = (const float4*)(data) + (size_t)g * 5;
        float4 q0 = __ldg(p + 0);
        float4 q1 = __ldg(p + 1);
        float4 q2 = __ldg(p + 2);
        float4 q3 = __ldg(p + 3);
        float4 q4 = __ldg(p + 4);
        int4 c = __ldg((const int4*)cid + g);

        // voxel layout: [d f0 f1 f2 f3] x4 -> features are cols 1..4
        atomicAdd(&s_sum[c.x * 4 + 0], q0.y);
        atomicAdd(&s_sum[c.x * 4 + 1], q0.z);
        atomicAdd(&s_sum[c.x * 4 + 2], q0.w);
        atomicAdd(&s_sum[c.x * 4 + 3], q1.x);
        atomicAdd(&s_cnt[c.x], 1.f);

        atomicAdd(&s_sum[c.y * 4 + 0], q1.z);
        atomicAdd(&s_sum[c.y * 4 + 1], q1.w);
        atomicAdd(&s_sum[c.y * 4 + 2], q2.x);
        atomicAdd(&s_sum[c.y * 4 + 3], q2.y);
        atomicAdd(&s_cnt[c.y], 1.f);

        atomicAdd(&s_sum[c.z * 4 + 0], q2.w);
        atomicAdd(&s_sum[c.z * 4 + 1], q3.x);
        atomicAdd(&s_sum[c.z * 4 + 2], q3.y);
        atomicAdd(&s_sum[c.z * 4 + 3], q3.z);
        atomicAdd(&s_cnt[c.z], 1.f);

        atomicAdd(&s_sum[c.w * 4 + 0], q4.x);
        atomicAdd(&s_sum[c.w * 4 + 1], q4.y);
        atomicAdd(&s_sum[c.w * 4 + 2], q4.z);
        atomicAdd(&s_sum[c.w * 4 + 3], q4.w);
        atomicAdd(&s_cnt[c.w], 1.f);
    }
    __syncthreads();

    float* gs = (float*)g_sum4;
    for (int i = threadIdx.x; i < NC * 4; i += 256) {
        float v = s_sum[i];
        if (v != 0.f) atomicAdd(&gs[i], v);
    }
    for (int i = threadIdx.x; i < NC; i += 256) {
        float v = s_cnt[i];
        if (v != 0.f) atomicAdd(&g_cnt[i], v);
    }
}

// ---------------------------------------------------------------------------
// Kernel 2: edge gather + 2-layer MLP.
// 32 edges/block, 128 threads, 52 KB smem -> grid=500, ~4 CTAs/SM resident.
//  Phase A: h[k][e] = relu(b1[k] + pooled[e].W1[:,k])  (k-major, [128][32])
//  Phase B: tile 4 edges x 4 outs per thread; conflict-free float4 LDS.
// ---------------------------------------------------------------------------
__global__ __launch_bounds__(128) void k_mlp(const int*   __restrict__ eidx,
                                             const float* __restrict__ W1,
                                             const float* __restrict__ b1,
                                             const float* __restrict__ W2,
                                             const float* __restrict__ b2,
                                             float*       __restrict__ out) {
    extern __shared__ float sm[];
    float* s_W2   = sm;                 // 8192 floats  [128][64]
    float* s_h    = sm + 8192;          // 4096 floats  [128][32] (k-major)
    float* s_W1   = sm + 12288;         // 512  floats  [4][128]
    float* s_b1   = s_W1 + 512;         // 128
    float* s_b2   = s_b1 + 128;         // 64
    float* s_pool = s_b2 + 64;          // 128 floats   [32][4]

    const int t = threadIdx.x;

    for (int i = t; i < 8192 / 4; i += 128)
        ((float4*)s_W2)[i] = ((const float4*)W2)[i];
    for (int i = t; i < 512 / 4; i += 128)
        ((float4*)s_W1)[i] = ((const float4*)W1)[i];
    if (t < 128) s_b1[t] = b1[t];
    if (t < 64)  s_b2[t] = b2[t];

    const int base = blockIdx.x * 32;

    // Gather + pool (threads 0..31, one edge each).
    if (t < 32) {
        int e = base + t;
        int a = eidx[e];
        int b = eidx[NE + e];
        float4 sa = g_sum4[a];
        float4 sb = g_sum4[b];
        float inv = 1.f / fmaxf(g_cnt[a] + g_cnt[b], 1.f);
        s_pool[t * 4 + 0] = (sa.x + sb.x) * inv;
        s_pool[t * 4 + 1] = (sa.y + sb.y) * inv;
        s_pool[t * 4 + 2] = (sa.z + sb.z) * inv;
        s_pool[t * 4 + 3] = (sa.w + sb.w) * inv;
    }
    __syncthreads();

    // Phase A: thread t -> edge e = t&31, k-quarter kq = t>>5 (32 k each).
    {
        int e  = t & 31;
        int kq = (t >> 5) * 32;
        float p0 = s_pool[e * 4 + 0];
        float p1 = s_pool[e * 4 + 1];
        float p2 = s_pool[e * 4 + 2];
        float p3 = s_pool[e * 4 + 3];
#pragma unroll 4
        for (int j = 0; j < 32; j++) {
            int k = kq + j;
            float h = s_b1[k]
                    + p0 * s_W1[0 * 128 + k]
                    + p1 * s_W1[1 * 128 + k]
                    + p2 * s_W1[2 * 128 + k]
                    + p3 * s_W1[3 * 128 + k];
            s_h[k * 32 + e] = fmaxf(h, 0.f);  // 32 consecutive floats: coalesced
        }
    }
    __syncthreads();

    // Phase B: tx = out group (4 cols, 16 groups), ty = edge group (4 rows, 8 groups)
    const int tx = t & 15;
    const int ty = t >> 4;
    float acc[4][4];
#pragma unroll
    for (int i = 0; i < 4; i++)
#pragma unroll
        for (int j = 0; j < 4; j++) acc[i][j] = 0.f;

    const float4* hf4 = (const float4*)s_h;    // [128][8]
    const float4* wf4 = (const float4*)s_W2;   // [128][16]
#pragma unroll 4
    for (int k = 0; k < 128; k++) {
        float4 w = wf4[k * 16 + tx];           // 16 distinct f4: conflict-free
        float4 h = hf4[k * 8 + ty];            // 8 distinct f4: broadcast pairs
        float hv[4] = {h.x, h.y, h.z, h.w};
#pragma unroll
        for (int i = 0; i < 4; i++) {
            acc[i][0] = fmaf(hv[i], w.x, acc[i][0]);
            acc[i][1] = fmaf(hv[i], w.y, acc[i][1]);
            acc[i][2] = fmaf(hv[i], w.z, acc[i][2]);
            acc[i][3] = fmaf(hv[i], w.w, acc[i][3]);
        }
    }

    float c0 = s_b2[tx * 4 + 0];
    float c1 = s_b2[tx * 4 + 1];
    float c2 = s_b2[tx * 4 + 2];
    float c3 = s_b2[tx * 4 + 3];
#pragma unroll
    for (int i = 0; i < 4; i++) {
        int e = base + ty * 4 + i;
        float4 o = make_float4(acc[i][0] + c0, acc[i][1] + c1,
                               acc[i][2] + c2, acc[i][3] + c3);
        ((float4*)out)[e * 16 + tx] = o;       // coalesced float4 store
    }
}

// ---------------------------------------------------------------------------
// Launch: memset accumulators -> segment sum -> edge MLP (graph-capturable)
// ---------------------------------------------------------------------------
extern "C" void kernel_launch(void* const* d_in, const int* in_sizes, int n_in,
                              void* d_out, int out_size) {
    const float* data = (const float*)d_in[0];
    const int*   cid  = (const int*)  d_in[1];
    const int*   eidx = (const int*)  d_in[2];
    const float* W1   = (const float*)d_in[3];
    const float* b1   = (const float*)d_in[4];
    const float* W2   = (const float*)d_in[5];
    const float* b2   = (const float*)d_in[6];
    float*       out  = (float*)d_out;

    cudaFuncSetAttribute(k_mlp, cudaFuncAttributeMaxDynamicSharedMemorySize, 53248);

    void *p_sum, *p_cnt;
    cudaGetSymbolAddress(&p_sum, g_sum4);
    cudaGetSymbolAddress(&p_cnt, g_cnt);
    cudaMemsetAsync(p_sum, 0, NC * sizeof(float4));
    cudaMemsetAsync(p_cnt, 0, NC * sizeof(float));

    k_seg<<<296, 256>>>(data, cid);
    k_mlp<<<NE / 32, 128, 52480>>>(eidx, W1, b1, W2, b2, out);
}

// round 5
// speedup vs baseline: 2.4842x; 1.0949x over previous
#include <cuda_runtime.h>

#define NV   2000000
#define NC   2000
#define NE   16000
#define NREP 64        // replicas per cluster to kill L2 atomic contention

// Scratch (no cudaMalloc allowed).
__device__ float4 g_rsum[NC * NREP];   // 2 MB  replicated sums [cluster][replica]
__device__ float  g_rcnt[NC * NREP];   // 512KB replicated counts
__device__ float4 g_sum4[NC];          // reduced sums
__device__ float  g_cnt[NC];           // reduced counts

__device__ __forceinline__ void red_v4(float4* a, float x, float y, float z, float w) {
    asm volatile("red.global.add.v4.f32 [%0], {%1,%2,%3,%4};"
                 :: "l"(a), "f"(x), "f"(y), "f"(z), "f"(w) : "memory");
}
__device__ __forceinline__ void red_f(float* a, float v) {
    asm volatile("red.global.add.f32 [%0], %1;" :: "l"(a), "f"(v) : "memory");
}

// ---------------------------------------------------------------------------
// Kernel 1: segment sum via replicated global vector reductions.
// Per 4 voxels: 6x LDG.128 + 4x red.v4 + 4x red.f32 (8 reduction lane-ops,
// vs 26 for the shared-ATOMS version). Replica chosen per-warp so concurrent
// same-cluster updates land on different addresses (~16 collisions max).
// ---------------------------------------------------------------------------
__global__ __launch_bounds__(256) void k_seg(const float* __restrict__ data,
                                             const int*   __restrict__ cid) {
    const int rep = (blockIdx.x * 8 + (threadIdx.x >> 5)) & (NREP - 1);
    const int NG = NV / 4;
    const int stride = gridDim.x * 256;
    for (int g = blockIdx.x * 256 + threadIdx.x; g < NG; g += stride) {
        const float4* p = (const float4*)data + (size_t)g * 5;
        float4 q0 = __ldg(p + 0);
        float4 q1 = __ldg(p + 1);
        float4 q2 = __ldg(p + 2);
        float4 q3 = __ldg(p + 3);
        float4 q4 = __ldg(p + 4);
        int4 c = __ldg((const int4*)cid + g);

        // voxel layout: [d f0 f1 f2 f3] x4 -> features are cols 1..4
        red_v4(&g_rsum[c.x * NREP + rep], q0.y, q0.z, q0.w, q1.x);
        red_v4(&g_rsum[c.y * NREP + rep], q1.z, q1.w, q2.x, q2.y);
        red_v4(&g_rsum[c.z * NREP + rep], q2.w, q3.x, q3.y, q3.z);
        red_v4(&g_rsum[c.w * NREP + rep], q4.x, q4.y, q4.z, q4.w);
        red_f(&g_rcnt[c.x * NREP + rep], 1.f);
        red_f(&g_rcnt[c.y * NREP + rep], 1.f);
        red_f(&g_rcnt[c.z * NREP + rep], 1.f);
        red_f(&g_rcnt[c.w * NREP + rep], 1.f);
    }
}

// ---------------------------------------------------------------------------
// Kernel 1b: collapse replicas. One warp per cluster; lane l takes replicas
// l and l+32 (coalesced: [cluster][replica] layout), butterfly shfl reduce.
// ---------------------------------------------------------------------------
__global__ __launch_bounds__(256) void k_reduce() {
    const int w = (blockIdx.x * 256 + threadIdx.x) >> 5;   // cluster id
    const int l = threadIdx.x & 31;
    if (w >= NC) return;

    float4 a = g_rsum[w * NREP + l];
    float4 b = g_rsum[w * NREP + 32 + l];
    float  cnt = g_rcnt[w * NREP + l] + g_rcnt[w * NREP + 32 + l];
    float4 s = make_float4(a.x + b.x, a.y + b.y, a.z + b.z, a.w + b.w);

#pragma unroll
    for (int off = 16; off > 0; off >>= 1) {
        s.x += __shfl_down_sync(0xffffffff, s.x, off);
        s.y += __shfl_down_sync(0xffffffff, s.y, off);
        s.z += __shfl_down_sync(0xffffffff, s.z, off);
        s.w += __shfl_down_sync(0xffffffff, s.w, off);
        cnt += __shfl_down_sync(0xffffffff, cnt, off);
    }
    if (l == 0) {
        g_sum4[w] = s;
        g_cnt[w]  = cnt;
    }
}

// ---------------------------------------------------------------------------
// Kernel 2: edge gather + 2-layer MLP.
// 64 edges/block, 256 threads, grid=250 (NE/64).
//  Phase A: h[k][e] = relu(b1[k] + pooled[e].W1[:,k])  (k-major, [128][64])
//  Phase B: tile 4 edges x 4 outs per thread; conflict-free float4 LDS.
// ---------------------------------------------------------------------------
__global__ __launch_bounds__(256) void k_mlp(const int*   __restrict__ eidx,
                                             const float* __restrict__ W1,
                                             const float* __restrict__ b1,
                                             const float* __restrict__ W2,
                                             const float* __restrict__ b2,
                                             float*       __restrict__ out) {
    extern __shared__ float sm[];
    float* s_W2   = sm;                 // 8192 floats  [128][64]
    float* s_h    = sm + 8192;          // 8192 floats  [128][64] (k-major)
    float* s_W1   = sm + 16384;         // 512  floats  [4][128]
    float* s_b1   = s_W1 + 512;         // 128
    float* s_b2   = s_b1 + 128;         // 64
    float* s_pool = s_b2 + 64;          // 320 floats   [64][5] (pad: stride 5)

    const int t = threadIdx.x;

    for (int i = t; i < 8192 / 4; i += 256)
        ((float4*)s_W2)[i] = ((const float4*)W2)[i];
    if (t < 128) ((float4*)s_W1)[t] = ((const float4*)W1)[t];
    if (t < 128) s_b1[t] = b1[t];
    if (t < 64)  s_b2[t] = b2[t];

    const int base = blockIdx.x * 64;

    // Gather + pool (threads 0..63, one edge each).
    if (t < 64) {
        int e = base + t;
        int a = eidx[e];
        int b = eidx[NE + e];
        float4 sa = g_sum4[a];
        float4 sb = g_sum4[b];
        float inv = 1.f / fmaxf(g_cnt[a] + g_cnt[b], 1.f);
        s_pool[t * 5 + 0] = (sa.x + sb.x) * inv;
        s_pool[t * 5 + 1] = (sa.y + sb.y) * inv;
        s_pool[t * 5 + 2] = (sa.z + sb.z) * inv;
        s_pool[t * 5 + 3] = (sa.w + sb.w) * inv;
    }
    __syncthreads();

    // Phase A: thread t -> edge e = t&63, k-group kq = (t>>6)*32.
    {
        int e  = t & 63;
        int kq = (t >> 6) * 32;
        float p0 = s_pool[e * 5 + 0];
        float p1 = s_pool[e * 5 + 1];
        float p2 = s_pool[e * 5 + 2];
        float p3 = s_pool[e * 5 + 3];
#pragma unroll 4
        for (int j = 0; j < 32; j++) {
            int k = kq + j;
            float h = s_b1[k]
                    + p0 * s_W1[0 * 128 + k]
                    + p1 * s_W1[1 * 128 + k]
                    + p2 * s_W1[2 * 128 + k]
                    + p3 * s_W1[3 * 128 + k];
            s_h[k * 64 + e] = fmaxf(h, 0.f);
        }
    }
    __syncthreads();

    // Phase B: tx = out group (16 x 4 cols), ty = edge group (16 x 4 edges).
    const int tx = t & 15;
    const int ty = t >> 4;
    float acc[4][4];
#pragma unroll
    for (int i = 0; i < 4; i++)
#pragma unroll
        for (int j = 0; j < 4; j++) acc[i][j] = 0.f;

    const float4* hf4 = (const float4*)s_h;    // [128][16]
    const float4* wf4 = (const float4*)s_W2;   // [128][16]
#pragma unroll 4
    for (int k = 0; k < 128; k++) {
        float4 w = wf4[k * 16 + tx];           // 16 distinct f4: conflict-free
        float4 h = hf4[k * 16 + ty];           // 2 distinct f4 per warp: broadcast
        float hv[4] = {h.x, h.y, h.z, h.w};
#pragma unroll
        for (int i = 0; i < 4; i++) {
            acc[i][0] = fmaf(hv[i], w.x, acc[i][0]);
            acc[i][1] = fmaf(hv[i], w.y, acc[i][1]);
            acc[i][2] = fmaf(hv[i], w.z, acc[i][2]);
            acc[i][3] = fmaf(hv[i], w.w, acc[i][3]);
        }
    }

    float c0 = s_b2[tx * 4 + 0];
    float c1 = s_b2[tx * 4 + 1];
    float c2 = s_b2[tx * 4 + 2];
    float c3 = s_b2[tx * 4 + 3];
#pragma unroll
    for (int i = 0; i < 4; i++) {
        int e = base + ty * 4 + i;
        float4 o = make_float4(acc[i][0] + c0, acc[i][1] + c1,
                               acc[i][2] + c2, acc[i][3] + c3);
        ((float4*)out)[e * 16 + tx] = o;       // coalesced float4 store
    }
}

// ---------------------------------------------------------------------------
// Launch: memset replicas -> segment sum -> reduce -> edge MLP
// ---------------------------------------------------------------------------
extern "C" void kernel_launch(void* const* d_in, const int* in_sizes, int n_in,
                              void* d_out, int out_size) {
    const float* data = (const float*)d_in[0];
    const int*   cid  = (const int*)  d_in[1];
    const int*   eidx = (const int*)  d_in[2];
    const float* W1   = (const float*)d_in[3];
    const float* b1   = (const float*)d_in[4];
    const float* W2   = (const float*)d_in[5];
    const float* b2   = (const float*)d_in[6];
    float*       out  = (float*)d_out;

    cudaFuncSetAttribute(k_mlp, cudaFuncAttributeMaxDynamicSharedMemorySize, 70656);

    void *p_rsum, *p_rcnt;
    cudaGetSymbolAddress(&p_rsum, g_rsum);
    cudaGetSymbolAddress(&p_rcnt, g_rcnt);
    cudaMemsetAsync(p_rsum, 0, NC * NREP * sizeof(float4));
    cudaMemsetAsync(p_rcnt, 0, NC * NREP * sizeof(float));

    k_seg<<<1184, 256>>>(data, cid);
    k_reduce<<<(NC * 32 + 255) / 256, 256>>>();
    k_mlp<<<NE / 64, 256, 70656>>>(eidx, W1, b1, W2, b2, out);
}

// round 6
// speedup vs baseline: 2.6740x; 1.0764x over previous
#include <cuda_runtime.h>

#define NV   2000000
#define NC   2000
#define NE   16000
#define NREP 32        // replicas per cluster (kills L2 atomic contention)

// Scratch (no cudaMalloc allowed).
__device__ float4       g_rsum[NC * NREP];  // 1 MB replicated sums
__device__ unsigned int g_icnt[NC];         // integer counts
__device__ float4       g_sum4[NC];         // reduced sums
__device__ float        g_cnt[NC];          // reduced counts (float)

__device__ __forceinline__ void red_v4(float4* a, float x, float y, float z, float w) {
    asm volatile("red.global.add.v4.f32 [%0], {%1,%2,%3,%4};"
                 :: "l"(a), "f"(x), "f"(y), "f"(z), "f"(w) : "memory");
}
__device__ __forceinline__ void red_u32(unsigned int* a, unsigned int v) {
    asm volatile("red.global.add.u32 [%0], %1;" :: "l"(a), "r"(v) : "memory");
}

// ---------------------------------------------------------------------------
// Kernel 1: segment sum.
//  - feature sums: replicated red.v4 to L2 (1 lane-op per voxel)
//  - counts: shared-memory int histogram (ATOMS pipe, parallel with REDG),
//    flushed once per block with red.u32.
// grid=296 -> ~6.6 iterations/thread so DRAM latency pipelines.
// ---------------------------------------------------------------------------
__global__ __launch_bounds__(256) void k_seg(const float* __restrict__ data,
                                             const int*   __restrict__ cid) {
    __shared__ unsigned int s_cnt[NC];   // 8 KB
    for (int i = threadIdx.x; i < NC; i += 256) s_cnt[i] = 0u;
    __syncthreads();

    const int rep = (blockIdx.x * 8 + (threadIdx.x >> 5)) & (NREP - 1);
    const int NG = NV / 4;
    const int stride = gridDim.x * 256;
#pragma unroll 2
    for (int g = blockIdx.x * 256 + threadIdx.x; g < NG; g += stride) {
        const float4* p = (const float4*)data + (size_t)g * 5;
        float4 q0 = __ldg(p + 0);
        float4 q1 = __ldg(p + 1);
        float4 q2 = __ldg(p + 2);
        float4 q3 = __ldg(p + 3);
        float4 q4 = __ldg(p + 4);
        int4 c = __ldg((const int4*)cid + g);

        // voxel layout: [d f0 f1 f2 f3] x4 -> features are cols 1..4
        red_v4(&g_rsum[c.x * NREP + rep], q0.y, q0.z, q0.w, q1.x);
        red_v4(&g_rsum[c.y * NREP + rep], q1.z, q1.w, q2.x, q2.y);
        red_v4(&g_rsum[c.z * NREP + rep], q2.w, q3.x, q3.y, q3.z);
        red_v4(&g_rsum[c.w * NREP + rep], q4.x, q4.y, q4.z, q4.w);

        atomicAdd(&s_cnt[c.x], 1u);
        atomicAdd(&s_cnt[c.y], 1u);
        atomicAdd(&s_cnt[c.z], 1u);
        atomicAdd(&s_cnt[c.w], 1u);
    }
    __syncthreads();

    for (int i = threadIdx.x; i < NC; i += 256) {
        unsigned int v = s_cnt[i];
        if (v) red_u32(&g_icnt[i], v);
    }
}

// ---------------------------------------------------------------------------
// Kernel 1b: collapse 32 replicas per cluster. One warp per cluster,
// lane l owns replica l (coalesced 512B per warp), butterfly reduce.
// ---------------------------------------------------------------------------
__global__ __launch_bounds__(256) void k_reduce() {
    const int c = (blockIdx.x * 256 + threadIdx.x) >> 5;
    const int l = threadIdx.x & 31;
    if (c >= NC) return;

    float4 s = g_rsum[c * NREP + l];
#pragma unroll
    for (int off = 16; off > 0; off >>= 1) {
        s.x += __shfl_down_sync(0xffffffff, s.x, off);
        s.y += __shfl_down_sync(0xffffffff, s.y, off);
        s.z += __shfl_down_sync(0xffffffff, s.z, off);
        s.w += __shfl_down_sync(0xffffffff, s.w, off);
    }
    if (l == 0) {
        g_sum4[c] = s;
        g_cnt[c]  = (float)g_icnt[c];
    }
}

// ---------------------------------------------------------------------------
// Kernel 2: edge gather + 2-layer MLP (R4 structure).
// 64 edges/block, 256 threads, grid=250.
// ---------------------------------------------------------------------------
__global__ __launch_bounds__(256) void k_mlp(const int*   __restrict__ eidx,
                                             const float* __restrict__ W1,
                                             const float* __restrict__ b1,
                                             const float* __restrict__ W2,
                                             const float* __restrict__ b2,
                                             float*       __restrict__ out) {
    extern __shared__ float sm[];
    float* s_W2   = sm;                 // 8192 floats  [128][64]
    float* s_h    = sm + 8192;          // 8192 floats  [128][64] (k-major)
    float* s_W1   = sm + 16384;         // 512  floats  [4][128]
    float* s_b1   = s_W1 + 512;         // 128
    float* s_b2   = s_b1 + 128;         // 64
    float* s_pool = s_b2 + 64;          // 320 floats   [64][5] (pad: stride 5)

    const int t = threadIdx.x;

    for (int i = t; i < 8192 / 4; i += 256)
        ((float4*)s_W2)[i] = ((const float4*)W2)[i];
    if (t < 128) ((float4*)s_W1)[t] = ((const float4*)W1)[t];
    if (t < 128) s_b1[t] = b1[t];
    if (t < 64)  s_b2[t] = b2[t];

    const int base = blockIdx.x * 64;

    if (t < 64) {
        int e = base + t;
        int a = eidx[e];
        int b = eidx[NE + e];
        float4 sa = g_sum4[a];
        float4 sb = g_sum4[b];
        float inv = 1.f / fmaxf(g_cnt[a] + g_cnt[b], 1.f);
        s_pool[t * 5 + 0] = (sa.x + sb.x) * inv;
        s_pool[t * 5 + 1] = (sa.y + sb.y) * inv;
        s_pool[t * 5 + 2] = (sa.z + sb.z) * inv;
        s_pool[t * 5 + 3] = (sa.w + sb.w) * inv;
    }
    __syncthreads();

    // Phase A
    {
        int e  = t & 63;
        int kq = (t >> 6) * 32;
        float p0 = s_pool[e * 5 + 0];
        float p1 = s_pool[e * 5 + 1];
        float p2 = s_pool[e * 5 + 2];
        float p3 = s_pool[e * 5 + 3];
#pragma unroll 4
        for (int j = 0; j < 32; j++) {
            int k = kq + j;
            float h = s_b1[k]
                    + p0 * s_W1[0 * 128 + k]
                    + p1 * s_W1[1 * 128 + k]
                    + p2 * s_W1[2 * 128 + k]
                    + p3 * s_W1[3 * 128 + k];
            s_h[k * 64 + e] = fmaxf(h, 0.f);
        }
    }
    __syncthreads();

    // Phase B
    const int tx = t & 15;
    const int ty = t >> 4;
    float acc[4][4];
#pragma unroll
    for (int i = 0; i < 4; i++)
#pragma unroll
        for (int j = 0; j < 4; j++) acc[i][j] = 0.f;

    const float4* hf4 = (const float4*)s_h;    // [128][16]
    const float4* wf4 = (const float4*)s_W2;   // [128][16]
#pragma unroll 4
    for (int k = 0; k < 128; k++) {
        float4 w = wf4[k * 16 + tx];
        float4 h = hf4[k * 16 + ty];
        float hv[4] = {h.x, h.y, h.z, h.w};
#pragma unroll
        for (int i = 0; i < 4; i++) {
            acc[i][0] = fmaf(hv[i], w.x, acc[i][0]);
            acc[i][1] = fmaf(hv[i], w.y, acc[i][1]);
            acc[i][2] = fmaf(hv[i], w.z, acc[i][2]);
            acc[i][3] = fmaf(hv[i], w.w, acc[i][3]);
        }
    }

    float c0 = s_b2[tx * 4 + 0];
    float c1 = s_b2[tx * 4 + 1];
    float c2 = s_b2[tx * 4 + 2];
    float c3 = s_b2[tx * 4 + 3];
#pragma unroll
    for (int i = 0; i < 4; i++) {
        int e = base + ty * 4 + i;
        float4 o = make_float4(acc[i][0] + c0, acc[i][1] + c1,
                               acc[i][2] + c2, acc[i][3] + c3);
        ((float4*)out)[e * 16 + tx] = o;
    }
}

// ---------------------------------------------------------------------------
// Launch: memsets -> segment sum -> reduce -> edge MLP (graph-capturable)
// ---------------------------------------------------------------------------
extern "C" void kernel_launch(void* const* d_in, const int* in_sizes, int n_in,
                              void* d_out, int out_size) {
    const float* data = (const float*)d_in[0];
    const int*   cid  = (const int*)  d_in[1];
    const int*   eidx = (const int*)  d_in[2];
    const float* W1   = (const float*)d_in[3];
    const float* b1   = (const float*)d_in[4];
    const float* W2   = (const float*)d_in[5];
    const float* b2   = (const float*)d_in[6];
    float*       out  = (float*)d_out;

    cudaFuncSetAttribute(k_mlp, cudaFuncAttributeMaxDynamicSharedMemorySize, 70656);

    void *p_rsum, *p_icnt;
    cudaGetSymbolAddress(&p_rsum, g_rsum);
    cudaGetSymbolAddress(&p_icnt, g_icnt);
    cudaMemsetAsync(p_rsum, 0, NC * NREP * sizeof(float4));
    cudaMemsetAsync(p_icnt, 0, NC * sizeof(unsigned int));

    k_seg<<<296, 256>>>(data, cid);
    k_reduce<<<(NC * 32 + 255) / 256, 256>>>();
    k_mlp<<<NE / 64, 256, 70656>>>(eidx, W1, b1, W2, b2, out);
}

// round 7
// speedup vs baseline: 2.7130x; 1.0146x over previous
#include <cuda_runtime.h>

#define NV   2000000
#define NC   2000
#define NE   16000
#define NREP 32        // replicas per cluster (kills L2 atomic contention)

// Scratch (no cudaMalloc allowed).
__device__ float4 g_rsum[NC * NREP];  // 1 MB replicated sums
__device__ float4 g_cnt4[NC / 4];     // counts, float4-packed for red.v4 flush
__device__ float4 g_sum4[NC];         // reduced sums

__device__ __forceinline__ void red_v4(float4* a, float x, float y, float z, float w) {
    asm volatile("red.global.add.v4.f32 [%0], {%1,%2,%3,%4};"
                 :: "l"(a), "f"(x), "f"(y), "f"(z), "f"(w) : "memory");
}

// Packed fp32x2 helpers (FFMA2 only reachable via PTX).
__device__ __forceinline__ unsigned long long pack2(float a, float b) {
    unsigned long long r;
    asm("mov.b64 %0, {%1, %2};" : "=l"(r) : "f"(a), "f"(b));
    return r;
}
__device__ __forceinline__ void unpack2(unsigned long long v, float& a, float& b) {
    asm("mov.b64 {%0, %1}, %2;" : "=f"(a), "=f"(b) : "l"(v));
}
__device__ __forceinline__ void ffma2(unsigned long long& d,
                                      unsigned long long a, unsigned long long b) {
    asm("fma.rn.f32x2 %0, %1, %2, %0;" : "+l"(d) : "l"(a), "l"(b));
}

// ---------------------------------------------------------------------------
// Kernel 1: segment sum.
//  - feature sums: replicated red.v4 to L2 (1 lane-op per voxel)
//  - counts: shared float histogram (ATOMS pipe, parallel with REDG),
//    flushed once per block as 500 red.v4 ops (4 clusters per op).
// grid=592 -> 4 CTAs/SM, ~3.3 iterations/thread: DRAM latency pipelines.
// ---------------------------------------------------------------------------
__global__ __launch_bounds__(256) void k_seg(const float* __restrict__ data,
                                             const int*   __restrict__ cid) {
    __shared__ float s_cnt[NC];   // 8 KB
    for (int i = threadIdx.x; i < NC; i += 256) s_cnt[i] = 0.f;
    __syncthreads();

    const int rep = (blockIdx.x * 8 + (threadIdx.x >> 5)) & (NREP - 1);
    const int NG = NV / 4;
    const int stride = gridDim.x * 256;
#pragma unroll 2
    for (int g = blockIdx.x * 256 + threadIdx.x; g < NG; g += stride) {
        const float4* p = (const float4*)data + (size_t)g * 5;
        float4 q0 = __ldg(p + 0);
        float4 q1 = __ldg(p + 1);
        float4 q2 = __ldg(p + 2);
        float4 q3 = __ldg(p + 3);
        float4 q4 = __ldg(p + 4);
        int4 c = __ldg((const int4*)cid + g);

        // voxel layout: [d f0 f1 f2 f3] x4 -> features are cols 1..4
        red_v4(&g_rsum[c.x * NREP + rep], q0.y, q0.z, q0.w, q1.x);
        red_v4(&g_rsum[c.y * NREP + rep], q1.z, q1.w, q2.x, q2.y);
        red_v4(&g_rsum[c.z * NREP + rep], q2.w, q3.x, q3.y, q3.z);
        red_v4(&g_rsum[c.w * NREP + rep], q4.x, q4.y, q4.z, q4.w);

        atomicAdd(&s_cnt[c.x], 1.f);
        atomicAdd(&s_cnt[c.y], 1.f);
        atomicAdd(&s_cnt[c.z], 1.f);
        atomicAdd(&s_cnt[c.w], 1.f);
    }
    __syncthreads();

    for (int i = threadIdx.x; i < NC / 4; i += 256) {
        float4 v = ((const float4*)s_cnt)[i];
        red_v4(&g_cnt4[i], v.x, v.y, v.z, v.w);
    }
}

// ---------------------------------------------------------------------------
// Kernel 1b: collapse 32 replicas per cluster. One warp per cluster,
// lane l owns replica l (coalesced 512B per warp), butterfly reduce.
// ---------------------------------------------------------------------------
__global__ __launch_bounds__(256) void k_reduce() {
    const int c = (blockIdx.x * 256 + threadIdx.x) >> 5;
    const int l = threadIdx.x & 31;
    if (c >= NC) return;

    float4 s = g_rsum[c * NREP + l];
#pragma unroll
    for (int off = 16; off > 0; off >>= 1) {
        s.x += __shfl_down_sync(0xffffffff, s.x, off);
        s.y += __shfl_down_sync(0xffffffff, s.y, off);
        s.z += __shfl_down_sync(0xffffffff, s.z, off);
        s.w += __shfl_down_sync(0xffffffff, s.w, off);
    }
    if (l == 0) g_sum4[c] = s;
}

// ---------------------------------------------------------------------------
// Kernel 2: edge gather + 2-layer MLP. 64 edges/block, 256 threads, grid=250.
// Phase B uses packed fp32x2 FFMA (exact fp32, half the FMA issue slots).
// ---------------------------------------------------------------------------
__global__ __launch_bounds__(256) void k_mlp(const int*   __restrict__ eidx,
                                             const float* __restrict__ W1,
                                             const float* __restrict__ b1,
                                             const float* __restrict__ W2,
                                             const float* __restrict__ b2,
                                             float*       __restrict__ out) {
    extern __shared__ float sm[];
    float* s_W2   = sm;                 // 8192 floats  [128][64]
    float* s_h    = sm + 8192;          // 8192 floats  [128][64] (k-major)
    float* s_W1   = sm + 16384;         // 512  floats  [4][128]
    float* s_b1   = s_W1 + 512;         // 128
    float* s_b2   = s_b1 + 128;         // 64
    float* s_pool = s_b2 + 64;          // 320 floats   [64][5] (pad: stride 5)

    const int t = threadIdx.x;

    for (int i = t; i < 8192 / 4; i += 256)
        ((float4*)s_W2)[i] = ((const float4*)W2)[i];
    if (t < 128) ((float4*)s_W1)[t] = ((const float4*)W1)[t];
    if (t < 128) s_b1[t] = b1[t];
    if (t < 64)  s_b2[t] = b2[t];

    const int base = blockIdx.x * 64;

    if (t < 64) {
        int e = base + t;
        int a = eidx[e];
        int b = eidx[NE + e];
        float4 sa = g_sum4[a];
        float4 sb = g_sum4[b];
        const float* cf = (const float*)g_cnt4;
        float inv = 1.f / fmaxf(cf[a] + cf[b], 1.f);
        s_pool[t * 5 + 0] = (sa.x + sb.x) * inv;
        s_pool[t * 5 + 1] = (sa.y + sb.y) * inv;
        s_pool[t * 5 + 2] = (sa.z + sb.z) * inv;
        s_pool[t * 5 + 3] = (sa.w + sb.w) * inv;
    }
    __syncthreads();

    // Phase A
    {
        int e  = t & 63;
        int kq = (t >> 6) * 32;
        float p0 = s_pool[e * 5 + 0];
        float p1 = s_pool[e * 5 + 1];
        float p2 = s_pool[e * 5 + 2];
        float p3 = s_pool[e * 5 + 3];
#pragma unroll 4
        for (int j = 0; j < 32; j++) {
            int k = kq + j;
            float h = s_b1[k]
                    + p0 * s_W1[0 * 128 + k]
                    + p1 * s_W1[1 * 128 + k]
                    + p2 * s_W1[2 * 128 + k]
                    + p3 * s_W1[3 * 128 + k];
            s_h[k * 64 + e] = fmaxf(h, 0.f);
        }
    }
    __syncthreads();

    // Phase B: 4 edges x 4 outs per thread, packed f32x2 accumulators.
    const int tx = t & 15;
    const int ty = t >> 4;
    unsigned long long acc[4][2];   // [edge][out-pair] : {o0,o1},{o2,o3}
#pragma unroll
    for (int i = 0; i < 4; i++) { acc[i][0] = 0ull; acc[i][1] = 0ull; }

    const float4* hf4 = (const float4*)s_h;    // [128][16]
    const float4* wf4 = (const float4*)s_W2;   // [128][16]
#pragma unroll 4
    for (int k = 0; k < 128; k++) {
        float4 w = wf4[k * 16 + tx];           // conflict-free
        float4 h = hf4[k * 16 + ty];           // broadcast
        unsigned long long w01 = pack2(w.x, w.y);
        unsigned long long w23 = pack2(w.z, w.w);
        float hv[4] = {h.x, h.y, h.z, h.w};
#pragma unroll
        for (int i = 0; i < 4; i++) {
            unsigned long long hh = pack2(hv[i], hv[i]);
            ffma2(acc[i][0], hh, w01);
            ffma2(acc[i][1], hh, w23);
        }
    }

    float c0 = s_b2[tx * 4 + 0];
    float c1 = s_b2[tx * 4 + 1];
    float c2 = s_b2[tx * 4 + 2];
    float c3 = s_b2[tx * 4 + 3];
#pragma unroll
    for (int i = 0; i < 4; i++) {
        int e = base + ty * 4 + i;
        float a0, a1, a2, a3;
        unpack2(acc[i][0], a0, a1);
        unpack2(acc[i][1], a2, a3);
        float4 o = make_float4(a0 + c0, a1 + c1, a2 + c2, a3 + c3);
        ((float4*)out)[e * 16 + tx] = o;
    }
}

// ---------------------------------------------------------------------------
// Launch: memsets -> segment sum -> reduce -> edge MLP (graph-capturable)
// ---------------------------------------------------------------------------
extern "C" void kernel_launch(void* const* d_in, const int* in_sizes, int n_in,
                              void* d_out, int out_size) {
    const float* data = (const float*)d_in[0];
    const int*   cid  = (const int*)  d_in[1];
    const int*   eidx = (const int*)  d_in[2];
    const float* W1   = (const float*)d_in[3];
    const float* b1   = (const float*)d_in[4];
    const float* W2   = (const float*)d_in[5];
    const float* b2   = (const float*)d_in[6];
    float*       out  = (float*)d_out;

    cudaFuncSetAttribute(k_mlp, cudaFuncAttributeMaxDynamicSharedMemorySize, 70656);

    void *p_rsum, *p_cnt;
    cudaGetSymbolAddress(&p_rsum, g_rsum);
    cudaGetSymbolAddress(&p_cnt, g_cnt4);
    cudaMemsetAsync(p_rsum, 0, NC * NREP * sizeof(float4));
    cudaMemsetAsync(p_cnt, 0, (NC / 4) * sizeof(float4));

    k_seg<<<592, 256>>>(data, cid);
    k_reduce<<<(NC * 32 + 255) / 256, 256>>>();
    k_mlp<<<NE / 64, 256, 70656>>>(eidx, W1, b1, W2, b2, out);
}